// round 16
// baseline (speedup 1.0000x reference)
#include <cuda_runtime.h>
#include <cstdint>

#define DM     64
#define NPTS   1323
#define NTHR   256
#define SPT    8                         // slots per thread (single-slot iterations)
#define SPB    (NTHR * SPT)              // 2048 slots per block = 8192 points
#define NBUF   3                         // cp.async pipeline depth (slots in flight)
#define MAXR   8                         // rows a block can span

// exact p/1323 for p < ~2^31 (magic: ceil(2^40/1323) = 831074549)
__device__ __forceinline__ unsigned rowof(unsigned p) {
    return (unsigned)(((unsigned long long)p * 831074549ull) >> 40);
}

__device__ __forceinline__ uint32_t smem_u32(const void* p) {
    uint32_t a;
    asm("{ .reg .u64 t; cvta.to.shared.u64 t, %1; cvt.u32.u64 %0, t; }" : "=r"(a) : "l"(p));
    return a;
}
__device__ __forceinline__ void cpasync16(uint32_t dst, const void* src) {
    asm volatile("cp.async.cg.shared.global [%0], [%1], 16;" :: "r"(dst), "l"(src) : "memory");
}
__device__ __forceinline__ void cpasync_commit() {
    asm volatile("cp.async.commit_group;" ::: "memory");
}
template <int N>
__device__ __forceinline__ void cpasync_wait() {
    asm volatile("cp.async.wait_group %0;" :: "n"(N) : "memory");
}

// one point through the inverse-Cholesky transform + gaussian
__device__ __forceinline__ float mvn_pt(float d0, float d1, float d2,
                                        float4 qa, float4 qb, float4 qc)
{
    d0 -= qa.x;
    d1 -= qa.y;
    d2 -= qa.z;
    float z0 = d0 * qa.w;
    float z1 = (d1 - qb.x * z0) * qb.y;
    float z2 = fmaf(-qb.w, z1, fmaf(-qb.z, z0, d2)) * qc.x;
    float maha = fmaf(z0, z0, fmaf(z1, z1, z2 * z2));
    return qc.y * __expf(-0.5f * maha);
}

struct SmemP { float4 qa[MAXR], qb[MAXR], qc[MAXR]; };

// one slot given staged data; params from block-local smem table
__device__ __forceinline__ float4 mvn_slot(unsigned s, unsigned r_first,
                                           float4 a, float4 b, float4 c,
                                           const SmemP* sp)
{
    const unsigned p0 = 4u * s;
    const unsigned r0 = rowof(p0);
    const unsigned rem = p0 - r0 * (unsigned)NPTS;   // p0 mod 1323
    const int i0 = (int)(r0 - r_first);

    const float4 qa = sp->qa[i0], qb = sp->qb[i0], qc = sp->qc[i0];

    float4 res;
    if (rem <= (unsigned)(NPTS - 4)) {
        // fast path (99.7%): all 4 points in row r0
        res.x = mvn_pt(a.x, a.y, a.z, qa, qb, qc);
        res.y = mvn_pt(a.w, b.x, b.y, qa, qb, qc);
        res.z = mvn_pt(b.z, b.w, c.x, qa, qb, qc);
        res.w = mvn_pt(c.y, c.z, c.w, qa, qb, qc);
    } else {
        // slot crosses into row r0+1
        const float4 qa2 = sp->qa[i0 + 1], qb2 = sp->qb[i0 + 1], qc2 = sp->qc[i0 + 1];
        res.x = (rem + 0 < (unsigned)NPTS) ? mvn_pt(a.x, a.y, a.z, qa, qb, qc)
                                           : mvn_pt(a.x, a.y, a.z, qa2, qb2, qc2);
        res.y = (rem + 1 < (unsigned)NPTS) ? mvn_pt(a.w, b.x, b.y, qa, qb, qc)
                                           : mvn_pt(a.w, b.x, b.y, qa2, qb2, qc2);
        res.z = (rem + 2 < (unsigned)NPTS) ? mvn_pt(b.z, b.w, c.x, qa, qb, qc)
                                           : mvn_pt(b.z, b.w, c.x, qa2, qb2, qc2);
        res.w = (rem + 3 < (unsigned)NPTS) ? mvn_pt(c.y, c.z, c.w, qa, qb, qc)
                                           : mvn_pt(c.y, c.z, c.w, qa2, qb2, qc2);
    }
    return res;
}

__global__ __launch_bounds__(NTHR, 5) void mvn_fused_kernel(
    const float* __restrict__ rep,
    const float* __restrict__ dxyz,
    const float* __restrict__ Wm,
    const float* __restrict__ bm,
    const float* __restrict__ bs_,
    const float* __restrict__ Ws,
    float* __restrict__ out,
    int nrows)
{
    __shared__ __align__(16) float4 sd[NBUF][NTHR * 3];   // 3 x 12KB staging buffers
    __shared__ SmemP sp;

    const int t = threadIdx.x;
    const int wid = t >> 5, lane = t & 31;

    const unsigned sBase = blockIdx.x * (unsigned)SPB;
    const unsigned r_first = rowof(4u * sBase);

    const float4* __restrict__ dp4 = (const float4*)dxyz;

    // my staging region in each buffer (48B per slot, conflict-free LDS.128 stride)
    uint32_t myDst[NBUF];
    #pragma unroll
    for (int b = 0; b < NBUF; b++) myDst[b] = smem_u32(&sd[b][3 * t]);

    // ---- pre-issue the first NBUF slots' copies (zero register cost in flight) ----
    #pragma unroll
    for (int j = 0; j < NBUF; j++) {
        const unsigned s = sBase + (unsigned)j * NTHR + (unsigned)t;
        const float4* src = dp4 + 3u * (size_t)s;
        cpasync16(myDst[j] + 0,  src + 0);
        cpasync16(myDst[j] + 16, src + 1);
        cpasync16(myDst[j] + 32, src + 2);
        cpasync_commit();
    }

    // ---- prologue: warp w computes params for row r_first + w (all warps parallel) ----
    {
        int r = (int)r_first + wid;
        if (r > nrows - 1) r = nrows - 1;
        const float2 v = ((const float2*)(rep + (size_t)r * DM))[lane];

        float dots[9];
        #pragma unroll
        for (int cc = 0; cc < 9; cc++) {
            const float* w = (cc < 3) ? (Wm + cc * DM) : (Ws + (cc - 3) * DM);
            const float2 wv = ((const float2*)w)[lane];
            float partial = fmaf(v.x, wv.x, v.y * wv.y);
            #pragma unroll
            for (int off = 16; off > 0; off >>= 1)
                partial += __shfl_xor_sync(0xFFFFFFFFu, partial, off);
            dots[cc] = partial;   // full sum on every lane
        }

        float sig = 0.0f, splus = 0.0f;
        if (lane < 6) {
            sig = 1.0f / (1.0f + __expf(-(dots[3 + lane] + bs_[lane])));
            splus = __logf(1.0f + __expf(sig));   // sig in (0,1): always safe
        }
        const float L00 = __shfl_sync(0xFFFFFFFFu, splus, 0);
        const float L10 = __shfl_sync(0xFFFFFFFFu, sig,   1);
        const float L11 = __shfl_sync(0xFFFFFFFFu, splus, 2);
        const float L20 = __shfl_sync(0xFFFFFFFFu, sig,   3);
        const float L21 = __shfl_sync(0xFFFFFFFFu, sig,   4);
        const float L22 = __shfl_sync(0xFFFFFFFFu, splus, 5);

        if (lane == 0) {
            const float TWO_PI_1P5 = 15.749609945722419f;   // (2*pi)^1.5
            const float C = 1.0f / (L00 * L11 * L22 * TWO_PI_1P5);
            sp.qa[wid] = make_float4(dots[0] + bm[0], dots[1] + bm[1], dots[2] + bm[2],
                                     1.0f / L00);
            sp.qb[wid] = make_float4(L10, 1.0f / L11, L20, L21);
            sp.qc[wid] = make_float4(1.0f / L22, C, 0.0f, 0.0f);
        }
    }
    __syncthreads();   // params ready; staging needs no barrier (thread-private regions)

    // ---- streaming: 8 slots, 3-deep cp.async pipeline, no barriers in loop ----
    #pragma unroll
    for (int i = 0; i < SPT; i++) {
        // wait until slot i's group is complete (groups newer than i stay pending)
        if      (i <= SPT - 1 - 2) cpasync_wait<2>();
        else if (i == SPT - 2)     cpasync_wait<1>();
        else                       cpasync_wait<0>();

        const float4* sb = &sd[i % NBUF][3 * t];
        const float4 a = sb[0];
        const float4 b = sb[1];
        const float4 c = sb[2];

        // refill this buffer with slot i+NBUF (issued after our reads of it)
        if (i + NBUF < SPT) {
            const unsigned sN = sBase + (unsigned)(i + NBUF) * NTHR + (unsigned)t;
            const float4* src = dp4 + 3u * (size_t)sN;
            const uint32_t d = myDst[i % NBUF];
            cpasync16(d + 0,  src + 0);
            cpasync16(d + 16, src + 1);
            cpasync16(d + 32, src + 2);
        }
        cpasync_commit();   // keep group count consistent every iteration

        const unsigned s = sBase + (unsigned)i * NTHR + (unsigned)t;
        __stcs((float4*)out + s, mvn_slot(s, r_first, a, b, c, &sp));
    }
}

extern "C" void kernel_launch(void* const* d_in, const int* in_sizes, int n_in,
                              void* d_out, int out_size)
{
    const float* rep  = (const float*)d_in[0];
    const float* dxyz = (const float*)d_in[1];
    const float* Wm   = (const float*)d_in[2];
    const float* bm   = (const float*)d_in[3];
    const float* Ws   = (const float*)d_in[4];
    const float* bs   = (const float*)d_in[5];
    // d_in[6] = num_planes (fixed 3) — unused

    float* out = (float*)d_out;

    const int nrows = in_sizes[0] / DM;                       // 16384
    const unsigned total_slots = (unsigned)nrows * NPTS / 4u; // 5419008
    const unsigned blocks = total_slots / SPB;                // 2646, exact
    mvn_fused_kernel<<<blocks, NTHR>>>(rep, dxyz, Wm, bm, bs, Ws, out, nrows);
}

// round 17
// speedup vs baseline: 1.3139x; 1.3139x over previous
#include <cuda_runtime.h>

#define DM     64
#define NPTS   1323
#define NTHR   256
#define SPT    8                         // slots per thread
#define SPB    (NTHR * SPT)              // 2048 slots per block = 8192 points
#define NPAIR  (SPT / 2)                 // 4 pair-iterations
#define MAXR   8                         // rows a block can span

// exact p/1323 for p < ~2^31 (magic: ceil(2^40/1323) = 831074549)
__device__ __forceinline__ unsigned rowof(unsigned p) {
    return (unsigned)(((unsigned long long)p * 831074549ull) >> 40);
}

// one point through the inverse-Cholesky transform + gaussian
__device__ __forceinline__ float mvn_pt(float d0, float d1, float d2,
                                        float4 qa, float4 qb, float4 qc)
{
    d0 -= qa.x;
    d1 -= qa.y;
    d2 -= qa.z;
    float z0 = d0 * qa.w;
    float z1 = (d1 - qb.x * z0) * qb.y;
    float z2 = fmaf(-qb.w, z1, fmaf(-qb.z, z0, d2)) * qc.x;
    float maha = fmaf(z0, z0, fmaf(z1, z1, z2 * z2));
    return qc.y * __expf(-0.5f * maha);
}

struct SmemP { float4 qa[MAXR], qb[MAXR], qc[MAXR]; };

// one slot given staged data; params from block-local smem table
__device__ __forceinline__ float4 mvn_slot(unsigned s, unsigned r_first,
                                           float4 a, float4 b, float4 c,
                                           const SmemP* sp)
{
    const unsigned p0 = 4u * s;
    const unsigned r0 = rowof(p0);
    const unsigned rem = p0 - r0 * (unsigned)NPTS;   // p0 mod 1323
    const int i0 = (int)(r0 - r_first);

    const float4 qa = sp->qa[i0], qb = sp->qb[i0], qc = sp->qc[i0];

    float4 res;
    if (rem <= (unsigned)(NPTS - 4)) {
        // fast path (99.7%): all 4 points in row r0
        res.x = mvn_pt(a.x, a.y, a.z, qa, qb, qc);
        res.y = mvn_pt(a.w, b.x, b.y, qa, qb, qc);
        res.z = mvn_pt(b.z, b.w, c.x, qa, qb, qc);
        res.w = mvn_pt(c.y, c.z, c.w, qa, qb, qc);
    } else {
        // slot crosses into row r0+1: points with rem+j >= NPTS use next row's params
        const float4 qa2 = sp->qa[i0 + 1], qb2 = sp->qb[i0 + 1], qc2 = sp->qc[i0 + 1];
        res.x = (rem + 0 < (unsigned)NPTS) ? mvn_pt(a.x, a.y, a.z, qa, qb, qc)
                                           : mvn_pt(a.x, a.y, a.z, qa2, qb2, qc2);
        res.y = (rem + 1 < (unsigned)NPTS) ? mvn_pt(a.w, b.x, b.y, qa, qb, qc)
                                           : mvn_pt(a.w, b.x, b.y, qa2, qb2, qc2);
        res.z = (rem + 2 < (unsigned)NPTS) ? mvn_pt(b.z, b.w, c.x, qa, qb, qc)
                                           : mvn_pt(b.z, b.w, c.x, qa2, qb2, qc2);
        res.w = (rem + 3 < (unsigned)NPTS) ? mvn_pt(c.y, c.z, c.w, qa, qb, qc)
                                           : mvn_pt(c.y, c.z, c.w, qa2, qb2, qc2);
    }
    return res;
}

__global__ __launch_bounds__(NTHR, 5) void mvn_fused_kernel(
    const float* __restrict__ rep,
    const float* __restrict__ dxyz,
    const float* __restrict__ Wm,
    const float* __restrict__ bm,
    const float* __restrict__ bs_,
    const float* __restrict__ Ws,
    float* __restrict__ out,
    int nrows)
{
    __shared__ SmemP sp;

    const int t = threadIdx.x;
    const int wid = t >> 5, lane = t & 31;

    const unsigned sBase = blockIdx.x * (unsigned)SPB;
    const unsigned r_first = rowof(4u * sBase);

    const float4* __restrict__ dp4 = (const float4*)dxyz;

    // ---- issue the first PAIR's 6 loads before the prologue ----
    unsigned s0 = sBase + (unsigned)t;
    unsigned s1 = s0 + NTHR;
    float4 a0 = __ldcs(dp4 + 3u * (size_t)s0 + 0);
    float4 b0 = __ldcs(dp4 + 3u * (size_t)s0 + 1);
    float4 c0 = __ldcs(dp4 + 3u * (size_t)s0 + 2);
    float4 a1 = __ldcs(dp4 + 3u * (size_t)s1 + 0);
    float4 b1 = __ldcs(dp4 + 3u * (size_t)s1 + 1);
    float4 c1 = __ldcs(dp4 + 3u * (size_t)s1 + 2);

    // ---- prologue: warp w computes params for row r_first + w (all warps parallel) ----
    {
        int r = (int)r_first + wid;
        if (r > nrows - 1) r = nrows - 1;
        const float2 v = ((const float2*)(rep + (size_t)r * DM))[lane];

        float dots[9];
        #pragma unroll
        for (int cc = 0; cc < 9; cc++) {
            const float* w = (cc < 3) ? (Wm + cc * DM) : (Ws + (cc - 3) * DM);
            const float2 wv = ((const float2*)w)[lane];
            float partial = fmaf(v.x, wv.x, v.y * wv.y);
            #pragma unroll
            for (int off = 16; off > 0; off >>= 1)
                partial += __shfl_xor_sync(0xFFFFFFFFu, partial, off);
            dots[cc] = partial;   // full sum on every lane
        }

        float sig = 0.0f, splus = 0.0f;
        if (lane < 6) {
            sig = 1.0f / (1.0f + __expf(-(dots[3 + lane] + bs_[lane])));
            splus = __logf(1.0f + __expf(sig));   // sig in (0,1): always safe
        }
        const float L00 = __shfl_sync(0xFFFFFFFFu, splus, 0);
        const float L10 = __shfl_sync(0xFFFFFFFFu, sig,   1);
        const float L11 = __shfl_sync(0xFFFFFFFFu, splus, 2);
        const float L20 = __shfl_sync(0xFFFFFFFFu, sig,   3);
        const float L21 = __shfl_sync(0xFFFFFFFFu, sig,   4);
        const float L22 = __shfl_sync(0xFFFFFFFFu, splus, 5);

        if (lane == 0) {
            const float TWO_PI_1P5 = 15.749609945722419f;   // (2*pi)^1.5
            const float C = 1.0f / (L00 * L11 * L22 * TWO_PI_1P5);
            sp.qa[wid] = make_float4(dots[0] + bm[0], dots[1] + bm[1], dots[2] + bm[2],
                                     1.0f / L00);
            sp.qb[wid] = make_float4(L10, 1.0f / L11, L20, L21);
            sp.qc[wid] = make_float4(1.0f / L22, C, 0.0f, 0.0f);
        }
    }
    __syncthreads();

    // ---- streaming: 4 iterations x 2 slots; NEXT pair's loads issued BEFORE stores ----
    #pragma unroll
    for (int i = 0; i < NPAIR; i++) {
        const float4 r0 = mvn_slot(s0, r_first, a0, b0, c0, &sp);
        const float4 r1 = mvn_slot(s1, r_first, a1, b1, c1, &sp);

        const unsigned w0 = s0, w1 = s1;
        if (i + 1 < NPAIR) {
            // get the next 6 loads into the LSU queue before the stores
            s0 += 2u * NTHR;
            s1 += 2u * NTHR;
            a0 = __ldcs(dp4 + 3u * (size_t)s0 + 0);
            b0 = __ldcs(dp4 + 3u * (size_t)s0 + 1);
            c0 = __ldcs(dp4 + 3u * (size_t)s0 + 2);
            a1 = __ldcs(dp4 + 3u * (size_t)s1 + 0);
            b1 = __ldcs(dp4 + 3u * (size_t)s1 + 1);
            c1 = __ldcs(dp4 + 3u * (size_t)s1 + 2);
        }

        __stcs((float4*)out + w0, r0);
        __stcs((float4*)out + w1, r1);
    }
}

extern "C" void kernel_launch(void* const* d_in, const int* in_sizes, int n_in,
                              void* d_out, int out_size)
{
    const float* rep  = (const float*)d_in[0];
    const float* dxyz = (const float*)d_in[1];
    const float* Wm   = (const float*)d_in[2];
    const float* bm   = (const float*)d_in[3];
    const float* Ws   = (const float*)d_in[4];
    const float* bs   = (const float*)d_in[5];
    // d_in[6] = num_planes (fixed 3) — unused

    float* out = (float*)d_out;

    const int nrows = in_sizes[0] / DM;                       // 16384
    const unsigned total_slots = (unsigned)nrows * NPTS / 4u; // 5419008
    const unsigned blocks = total_slots / SPB;                // 2646, exact
    mvn_fused_kernel<<<blocks, NTHR>>>(rep, dxyz, Wm, bm, bs, Ws, out, nrows);
}